// round 1
// baseline (speedup 1.0000x reference)
#include <cuda_runtime.h>
#include <cuda_bf16.h>
#include <math.h>

#define E_  30
#define NB_ 12
#define F_  1024
#define H_  32
#define B_  8192
#define L_  128
#define EPS_ 1e-12f

// scratch: normalized per-(e,b) mixing weights, (E, B, NB)
__device__ float g_w[E_ * B_ * NB_];

#define TB 128   // B-rows per block
#define KT 32    // K chunk

// ---------------------------------------------------------------------------
// Kernel A: per-emotion 2-layer MLP  ->  normalized weights g_w
// grid (B/TB, E), 256 threads
// ---------------------------------------------------------------------------
__global__ __launch_bounds__(256) void mlp_weights_kernel(
    const float* __restrict__ X,    // (B,F)
    const float* __restrict__ bw,   // (E,NB) (from (E,1,NB,1))
    const float* __restrict__ W1,   // (E,F,H)
    const float* __restrict__ b1,   // (E,H)
    const float* __restrict__ W2,   // (E,H,NB)
    const float* __restrict__ b2)   // (E,NB)
{
    __shared__ float Xs[TB][KT + 1];   // pad 33: conflict-free scalar STS + LDS
    __shared__ float Ws[KT][H_];       // 32x32
    __shared__ float W2s[H_ * NB_];    // 384
    __shared__ float b2s[NB_];

    const int e   = blockIdx.y;
    const int b0  = blockIdx.x * TB;
    const int tid = threadIdx.x;
    const int tx4 = (tid & 7) << 2;    // output col group (H)
    const int ty4 = (tid >> 3) << 2;   // output row group (B)

    float acc[4][4];
    #pragma unroll
    for (int i = 0; i < 4; i++)
        #pragma unroll
        for (int j = 0; j < 4; j++) acc[i][j] = 0.f;

    const float* __restrict__ W1e = W1 + (size_t)e * F_ * H_;

    for (int k0 = 0; k0 < F_; k0 += KT) {
        // stage X tile: 128x32 floats (1024 float4), coalesced
        #pragma unroll
        for (int i = 0; i < 4; i++) {
            int f  = i * 256 + tid;
            int bl = f >> 3;
            int kq = (f & 7) << 2;
            float4 v = *reinterpret_cast<const float4*>(
                &X[(size_t)(b0 + bl) * F_ + k0 + kq]);
            Xs[bl][kq + 0] = v.x; Xs[bl][kq + 1] = v.y;
            Xs[bl][kq + 2] = v.z; Xs[bl][kq + 3] = v.w;
        }
        // stage W1 tile: 32x32 floats (256 float4)
        {
            int kr = tid >> 3;
            int hq = (tid & 7) << 2;
            float4 v = *reinterpret_cast<const float4*>(
                &W1e[(size_t)(k0 + kr) * H_ + hq]);
            *reinterpret_cast<float4*>(&Ws[kr][hq]) = v;
        }
        __syncthreads();

        #pragma unroll
        for (int kk = 0; kk < KT; kk++) {
            float a[4];
            #pragma unroll
            for (int i = 0; i < 4; i++) a[i] = Xs[ty4 + i][kk];
            float4 wv = *reinterpret_cast<const float4*>(&Ws[kk][tx4]);
            float w[4] = {wv.x, wv.y, wv.z, wv.w};
            #pragma unroll
            for (int i = 0; i < 4; i++)
                #pragma unroll
                for (int j = 0; j < 4; j++)
                    acc[i][j] = fmaf(a[i], w[j], acc[i][j]);
        }
        __syncthreads();
    }

    // selu(acc + b1) -> Hs (reuse Xs)
    const float SELU_SCALE = 1.0507009873554805f;
    const float SELU_ALPHA = 1.6732632423543772f;
    #pragma unroll
    for (int i = 0; i < 4; i++) {
        #pragma unroll
        for (int j = 0; j < 4; j++) {
            int r = ty4 + i, c = tx4 + j;
            float v = acc[i][j] + __ldg(&b1[e * H_ + c]);
            v = (v > 0.f) ? SELU_SCALE * v
                          : SELU_SCALE * SELU_ALPHA * (expf(v) - 1.f);
            Xs[r][c] = v;
        }
    }
    // stage W2, b2
    for (int t = tid; t < H_ * NB_; t += 256)
        W2s[t] = W2[(size_t)e * H_ * NB_ + t];
    if (tid < NB_) b2s[tid] = b2[e * NB_ + tid];
    __syncthreads();

    if (tid < TB) {
        const int r = tid;
        // allW: L1-normalized exp of basic-emotion weights (all positive)
        float ew[NB_]; float s = 0.f;
        #pragma unroll
        for (int n = 0; n < NB_; n++) { ew[n] = expf(bw[e * NB_ + n]); s += ew[n]; }
        const float inv_s = 1.f / fmaxf(s, EPS_);

        float upd[NB_]; float sa = 0.f;
        #pragma unroll
        for (int n = 0; n < NB_; n++) {
            float a2 = b2s[n];
            #pragma unroll
            for (int hh = 0; hh < H_; hh++)
                a2 = fmaf(Xs[r][hh], W2s[hh * NB_ + n], a2);
            float u = fmaf(ew[n], inv_s, a2);
            upd[n] = u;
            sa += fabsf(u);
        }
        const float inv = 1.f / fmaxf(sa, EPS_);
        float o[NB_];
        #pragma unroll
        for (int n = 0; n < NB_; n++) o[n] = upd[n] * inv;

        float4* dst = reinterpret_cast<float4*>(
            &g_w[((size_t)e * B_ + b0 + r) * NB_]);  // 48B-aligned
        dst[0] = make_float4(o[0], o[1], o[2],  o[3]);
        dst[1] = make_float4(o[4], o[5], o[6],  o[7]);
        dst[2] = make_float4(o[8], o[9], o[10], o[11]);
    }
}

// ---------------------------------------------------------------------------
// Kernel B: mixed = w @ D, softmax over L. grid (B), 128 threads (one per l)
// ---------------------------------------------------------------------------
__global__ __launch_bounds__(128) void mix_softmax_kernel(
    const float* __restrict__ D,   // (B, NB, L)
    float* __restrict__ out)       // (E, B, L)
{
    __shared__ float Ds[NB_ * L_];   // 6 KB
    __shared__ float ws[NB_];
    __shared__ float redmax[4];
    __shared__ float redsum[4];

    const int b   = blockIdx.x;
    const int tid = threadIdx.x;

    // stage D[b]: 1536 floats = 384 float4
    const float4* src = reinterpret_cast<const float4*>(&D[(size_t)b * NB_ * L_]);
    #pragma unroll
    for (int i = 0; i < 3; i++)
        reinterpret_cast<float4*>(Ds)[i * 128 + tid] = src[i * 128 + tid];

    for (int e = 0; e < E_; e++) {
        __syncthreads();  // Ds ready (e=0) / prev-iter readers done before ws overwrite
        if (tid < NB_) ws[tid] = g_w[((size_t)e * B_ + b) * NB_ + tid];
        __syncthreads();

        float v = 0.f;
        #pragma unroll
        for (int n = 0; n < NB_; n++) v = fmaf(ws[n], Ds[n * L_ + tid], v);

        // block max over 128 lanes
        float m = v;
        #pragma unroll
        for (int off = 16; off > 0; off >>= 1)
            m = fmaxf(m, __shfl_xor_sync(0xffffffffu, m, off));
        if ((tid & 31) == 0) redmax[tid >> 5] = m;
        __syncthreads();
        m = fmaxf(fmaxf(redmax[0], redmax[1]), fmaxf(redmax[2], redmax[3]));

        float ev = expf(v - m);
        float sm = ev;
        #pragma unroll
        for (int off = 16; off > 0; off >>= 1)
            sm += __shfl_xor_sync(0xffffffffu, sm, off);
        if ((tid & 31) == 0) redsum[tid >> 5] = sm;
        __syncthreads();
        sm = redsum[0] + redsum[1] + redsum[2] + redsum[3];

        out[((size_t)e * B_ + b) * L_ + tid] = ev / sm;
    }
}

// ---------------------------------------------------------------------------
extern "C" void kernel_launch(void* const* d_in, const int* in_sizes, int n_in,
                              void* d_out, int out_size)
{
    const float* D  = (const float*)d_in[0];  // basicEmotionDistributions (B,NB,L)
    const float* X  = (const float*)d_in[1];  // encodedFeatures (B,F)
    const float* bw = (const float*)d_in[2];  // allBasicEmotionWeights (E,1,NB,1)
    const float* W1 = (const float*)d_in[3];  // (E,F,H)
    const float* b1 = (const float*)d_in[4];  // (E,H)
    const float* W2 = (const float*)d_in[5];  // (E,H,NB)
    const float* b2 = (const float*)d_in[6];  // (E,NB)
    float* out = (float*)d_out;               // (E,B,L)

    dim3 gA(B_ / TB, E_);
    mlp_weights_kernel<<<gA, 256>>>(X, bw, W1, b1, W2, b2);
    mix_softmax_kernel<<<B_, 128>>>(D, out);
}

// round 2
// speedup vs baseline: 1.0429x; 1.0429x over previous
#include <cuda_runtime.h>
#include <cuda_bf16.h>
#include <math.h>

#define E_  30
#define NB_ 12
#define F_  1024
#define H_  32
#define B_  8192
#define L_  128
#define EPS_ 1e-12f

// scratch: normalized per-(e,b) mixing weights, (E, B, NB)
__device__ float g_w[E_ * B_ * NB_];

#define TB 256   // B-rows per block (== threads)
#define KT 32    // K chunk

// packed dual-FMA (Blackwell f32x2) — ptxas never emits this from C++
__device__ __forceinline__ void fma2(unsigned long long& d,
                                     unsigned long long a,
                                     unsigned long long b) {
    asm("fma.rn.f32x2 %0, %1, %2, %0;" : "+l"(d) : "l"(a), "l"(b));
}
__device__ __forceinline__ unsigned long long pack2(float lo, float hi) {
    unsigned long long r;
    asm("mov.b64 %0, {%1, %2};" : "=l"(r) : "f"(lo), "f"(hi));
    return r;
}
__device__ __forceinline__ void unpack2(float& lo, float& hi, unsigned long long v) {
    asm("mov.b64 {%0, %1}, %2;" : "=f"(lo), "=f"(hi) : "l"(v));
}

// ---------------------------------------------------------------------------
// Kernel A: per-emotion 2-layer MLP -> normalized weights g_w
// grid (B/TB, E), 256 threads. 256x32 output tile, 8x4 per thread, FFMA2.
// ---------------------------------------------------------------------------
__global__ __launch_bounds__(256) void mlp_weights_kernel(
    const float* __restrict__ X,    // (B,F)
    const float* __restrict__ bw,   // (E,NB)
    const float* __restrict__ W1,   // (E,F,H)
    const float* __restrict__ b1,   // (E,H)
    const float* __restrict__ W2,   // (E,H,NB)
    const float* __restrict__ b2)   // (E,NB)
{
    // ShA: mainloop = X tile, k-major [KT][TB] with XOR swizzle (32KB);
    //      epilogue = H tile [TB][33] (33.8KB)
    __shared__ __align__(16) float ShA[TB * 33];
    __shared__ __align__(16) float Ws[KT * H_];   // 32x32
    __shared__ float W2s[H_ * NB_];
    __shared__ float b2s[NB_];

    const int e   = blockIdx.y;
    const int b0  = blockIdx.x * TB;
    const int tid = threadIdx.x;
    const int tx4 = (tid & 7) << 2;    // col group (H)
    const int ty8 = (tid >> 3) << 3;   // row group (B), 8 rows

    // stage W2/b2 once (covered by first loop barrier)
    for (int t = tid; t < H_ * NB_; t += 256)
        W2s[t] = W2[(size_t)e * H_ * NB_ + t];
    if (tid < NB_) b2s[tid] = b2[e * NB_ + tid];

    unsigned long long acc[4][4];   // 4 row-pairs x 4 cols
    #pragma unroll
    for (int p = 0; p < 4; p++)
        #pragma unroll
        for (int j = 0; j < 4; j++) acc[p][j] = 0ull;

    const float* __restrict__ W1e = W1 + (size_t)e * F_ * H_;

    for (int k0 = 0; k0 < F_; k0 += KT) {
        __syncthreads();
        // stage X tile 256x32, k-major swizzled: elem(k,r) at ShA[k*TB + (r ^ (k&28))]
        #pragma unroll
        for (int it = 0; it < 8; it++) {
            int g   = it * 256 + tid;
            int row = g >> 3;
            int kq  = (g & 7) << 2;
            float4 v = *reinterpret_cast<const float4*>(
                &X[(size_t)(b0 + row) * F_ + k0 + kq]);
            int col = row ^ (kq & 28);   // kq+j has same &28
            ShA[(kq + 0) * TB + col] = v.x;
            ShA[(kq + 1) * TB + col] = v.y;
            ShA[(kq + 2) * TB + col] = v.z;
            ShA[(kq + 3) * TB + col] = v.w;
        }
        // stage W1 tile 32x32
        {
            int kr = tid >> 3;
            int hq = (tid & 7) << 2;
            *reinterpret_cast<float4*>(&Ws[kr * H_ + hq]) =
                *reinterpret_cast<const float4*>(&W1e[(size_t)(k0 + kr) * H_ + hq]);
        }
        __syncthreads();

        #pragma unroll
        for (int kk = 0; kk < KT; kk++) {
            const int s = kk & 28;
            // rows ty8..ty8+3 and ty8+4..ty8+7, already packed as f32 pairs
            ulonglong2 A0 = *reinterpret_cast<const ulonglong2*>(
                &ShA[kk * TB + (ty8 ^ s)]);
            ulonglong2 A1 = *reinterpret_cast<const ulonglong2*>(
                &ShA[kk * TB + ((ty8 + 4) ^ s)]);
            float4 wv = *reinterpret_cast<const float4*>(&Ws[kk * H_ + tx4]);
            unsigned long long wd0 = pack2(wv.x, wv.x);
            unsigned long long wd1 = pack2(wv.y, wv.y);
            unsigned long long wd2 = pack2(wv.z, wv.z);
            unsigned long long wd3 = pack2(wv.w, wv.w);
            fma2(acc[0][0], A0.x, wd0); fma2(acc[0][1], A0.x, wd1);
            fma2(acc[0][2], A0.x, wd2); fma2(acc[0][3], A0.x, wd3);
            fma2(acc[1][0], A0.y, wd0); fma2(acc[1][1], A0.y, wd1);
            fma2(acc[1][2], A0.y, wd2); fma2(acc[1][3], A0.y, wd3);
            fma2(acc[2][0], A1.x, wd0); fma2(acc[2][1], A1.x, wd1);
            fma2(acc[2][2], A1.x, wd2); fma2(acc[2][3], A1.x, wd3);
            fma2(acc[3][0], A1.y, wd0); fma2(acc[3][1], A1.y, wd1);
            fma2(acc[3][2], A1.y, wd2); fma2(acc[3][3], A1.y, wd3);
        }
    }
    __syncthreads();   // mainloop reads of ShA done; switch to H-tile view

    // selu(acc + b1) -> Hs[TB][33]
    const float SELU_SCALE  = 1.0507009873554805f;
    const float SELU_SA     = 1.0507009873554805f * 1.6732632423543772f;
    #pragma unroll
    for (int j = 0; j < 4; j++) {
        const int   c  = tx4 + j;
        const float bc = __ldg(&b1[e * H_ + c]);
        #pragma unroll
        for (int p = 0; p < 4; p++) {
            float lo, hi;
            unpack2(lo, hi, acc[p][j]);
            float v0 = lo + bc, v1 = hi + bc;
            v0 = (v0 > 0.f) ? SELU_SCALE * v0 : SELU_SA * (__expf(v0) - 1.f);
            v1 = (v1 > 0.f) ? SELU_SCALE * v1 : SELU_SA * (__expf(v1) - 1.f);
            ShA[(ty8 + 2 * p + 0) * 33 + c] = v0;
            ShA[(ty8 + 2 * p + 1) * 33 + c] = v1;
        }
    }
    __syncthreads();

    // second layer + weight update + signed L1-normalize: thread = one B-row
    {
        const int r = tid;
        float hr[H_];
        #pragma unroll
        for (int hh = 0; hh < H_; hh++) hr[hh] = ShA[r * 33 + hh];

        float ew[NB_]; float s = 0.f;
        #pragma unroll
        for (int n = 0; n < NB_; n++) {
            ew[n] = __expf(__ldg(&bw[e * NB_ + n]));
            s += ew[n];
        }
        const float inv_s = 1.f / fmaxf(s, EPS_);

        float upd[NB_]; float sa = 0.f;
        #pragma unroll
        for (int n = 0; n < NB_; n++) {
            float a2 = b2s[n];
            #pragma unroll
            for (int hh = 0; hh < H_; hh++)
                a2 = fmaf(hr[hh], W2s[hh * NB_ + n], a2);
            float u = fmaf(ew[n], inv_s, a2);
            upd[n] = u;
            sa += fabsf(u);
        }
        const float inv = 1.f / fmaxf(sa, EPS_);

        float4* dst = reinterpret_cast<float4*>(
            &g_w[((size_t)e * B_ + b0 + r) * NB_]);
        dst[0] = make_float4(upd[0] * inv, upd[1] * inv, upd[2]  * inv, upd[3]  * inv);
        dst[1] = make_float4(upd[4] * inv, upd[5] * inv, upd[6]  * inv, upd[7]  * inv);
        dst[2] = make_float4(upd[8] * inv, upd[9] * inv, upd[10] * inv, upd[11] * inv);
    }
}

// ---------------------------------------------------------------------------
// Kernel B: mixed = w @ D, softmax over L. One warp per b, lane holds 4 l's.
// grid (B/4), 128 threads. D stays in registers; warp-only reductions.
// ---------------------------------------------------------------------------
__global__ __launch_bounds__(128) void mix_softmax_kernel(
    const float* __restrict__ D,   // (B, NB, L)
    float* __restrict__ out)       // (E, B, L)
{
    __shared__ float ws_s[4][NB_];

    const int tid  = threadIdx.x;
    const int warp = tid >> 5;
    const int lane = tid & 31;
    const int b    = blockIdx.x * 4 + warp;

    // D[b] in registers: lane owns columns lane*4..lane*4+3
    float4 Dreg[NB_];
    #pragma unroll
    for (int n = 0; n < NB_; n++)
        Dreg[n] = *reinterpret_cast<const float4*>(
            &D[((size_t)b * NB_ + n) * L_ + lane * 4]);

    for (int e = 0; e < E_; e++) {
        if (lane < NB_)
            ws_s[warp][lane] = g_w[((size_t)e * B_ + b) * NB_ + lane];
        __syncwarp();

        float4 v = make_float4(0.f, 0.f, 0.f, 0.f);
        #pragma unroll
        for (int n = 0; n < NB_; n++) {
            float wn = ws_s[warp][n];
            v.x = fmaf(wn, Dreg[n].x, v.x);
            v.y = fmaf(wn, Dreg[n].y, v.y);
            v.z = fmaf(wn, Dreg[n].z, v.z);
            v.w = fmaf(wn, Dreg[n].w, v.w);
        }
        __syncwarp();   // reads done before next-iter overwrite

        float m = fmaxf(fmaxf(v.x, v.y), fmaxf(v.z, v.w));
        #pragma unroll
        for (int off = 16; off > 0; off >>= 1)
            m = fmaxf(m, __shfl_xor_sync(0xffffffffu, m, off));

        float e0 = __expf(v.x - m), e1 = __expf(v.y - m);
        float e2 = __expf(v.z - m), e3 = __expf(v.w - m);
        float sm = e0 + e1 + e2 + e3;
        #pragma unroll
        for (int off = 16; off > 0; off >>= 1)
            sm += __shfl_xor_sync(0xffffffffu, sm, off);

        const float inv = 1.f / sm;
        *reinterpret_cast<float4*>(&out[((size_t)e * B_ + b) * L_ + lane * 4]) =
            make_float4(e0 * inv, e1 * inv, e2 * inv, e3 * inv);
    }
}

// ---------------------------------------------------------------------------
extern "C" void kernel_launch(void* const* d_in, const int* in_sizes, int n_in,
                              void* d_out, int out_size)
{
    const float* D  = (const float*)d_in[0];  // (B,NB,L)
    const float* X  = (const float*)d_in[1];  // (B,F)
    const float* bw = (const float*)d_in[2];  // (E,1,NB,1)
    const float* W1 = (const float*)d_in[3];  // (E,F,H)
    const float* b1 = (const float*)d_in[4];  // (E,H)
    const float* W2 = (const float*)d_in[5];  // (E,H,NB)
    const float* b2 = (const float*)d_in[6];  // (E,NB)
    float* out = (float*)d_out;               // (E,B,L)

    dim3 gA(B_ / TB, E_);
    mlp_weights_kernel<<<gA, 256>>>(X, bw, W1, b1, W2, b2);
    mix_softmax_kernel<<<B_ / 4, 128>>>(D, out);
}